// round 12
// baseline (speedup 1.0000x reference)
#include <cuda_runtime.h>
#include <cstdint>

// Problem constants (fixed by the reference).
#define BB 32
#define TT 2000
#define LL 256
#define HH 512
#define NTHR 256
#define FRAMES_PER_THR 8   // 256*8 = 2048 >= 2000
#define T4 (TT / 4)        // 500 float4 groups
#define THRESH 0.95f
#define NTOK (BB * LL)     // 8192 tokens
#define GBLK 1184          // 148 SMs * 8 CTAs (x4 warps = 4736 stealing warps)

// Prefetch role: 512 blocks = 16 per batch; each block pulls 128 KB of the
// FIRST 2 MB (first 1024 frames) of its batch into L2. Total 64 MB ~= the
// serial scan's DRAM shadow (~14 us at ~4.5 TB/s).
#define NPF 512
#define PF_PER_THR 4

// Scratch (allocation-free rule: __device__ globals).
__device__ float g_walpha[BB * TT];   // rescaled alphas
__device__ int4  g_rec[BB * LL];      // {seg_start, seg_end, carry_bits, cur_bits}
__device__ int   g_cnt[BB];           // fires per batch (clamped to LL)
__device__ int   g_work;              // work-stealing counter (reset by scan)

// One CIF recurrence step, forced to the short data chain:
//   add.f32 -> {setp.ge ; sub.f32 in parallel} -> selp.f32 (pred-as-data)
__device__ __forceinline__ void cif_step(float& integ, float a, float& ni_out)
{
    float ni, nim;
    asm("add.f32 %0, %2, %3;\n\t"
        "sub.f32 %1, %0, 0f3F800000;"            // nim = ni - 1.0f
        : "=f"(ni), "=f"(nim) : "f"(integ), "f"(a));
    asm("{\n\t"
        ".reg .pred p;\n\t"
        "setp.ge.f32 p, %1, 0f3F733333;\n\t"     // ni >= 0.95f
        "selp.f32 %0, %2, %1, p;\n\t"
        "}"
        : "=f"(integ) : "f"(ni), "f"(nim));
    ni_out = ni;
}

// ---------------------------------------------------------------------------
// Kernel 1: blocks [0,32) = scan role. Blocks [32, 32+NPF) = L2 prefetch of
// the first 1024 frames of each batch (matches gather's ascending-k order).
// ---------------------------------------------------------------------------
__global__ void __launch_bounds__(NTHR, 1) cif_scan_kernel(
    const float* __restrict__ hidden,   // [B,T,H] (prefetch only)
    const float* __restrict__ alphas,   // [B,T]
    const int*   __restrict__ tlen)     // [B]
{
    const int tid = threadIdx.x;

    if (blockIdx.x >= BB) {
        // ---- Prefetch role ----
        const int p  = blockIdx.x - BB;       // 0..511
        const int pb = p >> 4;                // batch 0..31
        const int pj = p & 15;                // 128KB slice within first 2MB
        const size_t base = (size_t)pb * (TT * HH * 4)
                          + (size_t)pj * (NTHR * PF_PER_THR * 128)
                          + (size_t)tid * 128;
        const char* q = reinterpret_cast<const char*>(hidden) + base;
        #pragma unroll
        for (int i = 0; i < PF_PER_THR; ++i)
            asm volatile("prefetch.global.L2 [%0];"
                         :: "l"(q + (size_t)i * NTHR * 128));
        return;
    }

    __shared__ __align__(16) float s_alpha[TT];
    __shared__ __align__(16) float s_ni[TT];
    __shared__ double s_wred[8];
    __shared__ float  s_scale;
    __shared__ int    s_tsum[NTHR];
    __shared__ int    s_fidx[LL];
    __shared__ int    s_cnt;

    const int b    = blockIdx.x;
    const int lane = tid & 31;
    const int wid  = tid >> 5;

    if (b == 0 && tid == 0) g_work = 0;   // reset for the following gather

    // ---- Phase 1: load alphas (float4), double sum via warp shuffles ----
    const float4* ain = reinterpret_cast<const float4*>(alphas + b * TT);
    float4* asm4 = reinterpret_cast<float4*>(s_alpha);
    double local = 0.0;
    #pragma unroll
    for (int i = 0; i < 2; ++i) {
        const int idx = tid + i * NTHR;
        if (idx < T4) {
            const float4 v = ain[idx];
            asm4[idx] = v;
            local += (double)v.x + (double)v.y + (double)v.z + (double)v.w;
        }
    }
    #pragma unroll
    for (int off = 16; off > 0; off >>= 1)
        local += __shfl_down_sync(0xffffffffu, local, off);
    if (lane == 0) s_wred[wid] = local;
    __syncthreads();
    if (tid == 0) {
        double s = 0.0;
        #pragma unroll
        for (int w = 0; w < 8; ++w) s += s_wred[w];
        s_scale = __fdiv_rn((float)tlen[b], (float)s);
    }
    __syncthreads();

    // ---- Rescale (smem + spill to global) ----
    const float scale = s_scale;
    float4* wout = reinterpret_cast<float4*>(g_walpha + b * TT);
    #pragma unroll
    for (int i = 0; i < 2; ++i) {
        const int idx = tid + i * NTHR;
        if (idx < T4) {
            float4 v = asm4[idx];
            v.x = __fmul_rn(v.x, scale); v.y = __fmul_rn(v.y, scale);
            v.z = __fmul_rn(v.z, scale); v.w = __fmul_rn(v.w, scale);
            asm4[idx] = v;
            wout[idx] = v;
        }
    }
    __syncthreads();

    // ---- Phase 2: minimal serial recurrence (thread 0), prefetched ----
    if (tid == 0) {
        float integ = 0.0f;
        const float4* a4 = reinterpret_cast<const float4*>(s_alpha);
        float4* n4 = reinterpret_cast<float4*>(s_ni);
        float4 av = a4[0];
        #pragma unroll 2
        for (int t4 = 0; t4 < T4; ++t4) {
            const int nidx = (t4 + 1 < T4) ? t4 + 1 : t4;
            const float4 nx = a4[nidx];       // prefetch off-chain
            float4 nv;
            cif_step(integ, av.x, nv.x);
            cif_step(integ, av.y, nv.y);
            cif_step(integ, av.z, nv.z);
            cif_step(integ, av.w, nv.w);
            n4[t4] = nv;
            av = nx;
        }
    }
    __syncthreads();

    // ---- Phase 3: parallel rebuild of fire records from ni_t ----
    const int t0 = tid * FRAMES_PER_THR;
    int cnt_local = 0;
    #pragma unroll
    for (int j = 0; j < FRAMES_PER_THR; ++j) {
        const int t = t0 + j;
        if (t < TT && s_ni[t] >= THRESH) ++cnt_local;
    }
    s_tsum[tid] = cnt_local;
    __syncthreads();

    {   // exclusive prefix sum over 256 counts
        int v = s_tsum[tid];
        int x = v;
        #pragma unroll
        for (int d = 1; d < 32; d <<= 1) {
            int y = __shfl_up_sync(0xffffffffu, x, d);
            if (lane >= d) x += y;
        }
        __syncthreads();
        if (lane == 31) s_tsum[wid] = x;
        __syncthreads();
        int warp_base = 0, total = 0;
        #pragma unroll
        for (int w = 0; w < 8; ++w) {
            const int wv = s_tsum[w];
            warp_base += (w < wid) ? wv : 0;
            total += wv;
        }
        __syncthreads();
        s_tsum[tid] = warp_base + x - v;
        if (tid == 0) s_cnt = (total < LL) ? total : LL;
    }
    __syncthreads();

    {   // compact fire frame indices
        int k = s_tsum[tid];
        #pragma unroll
        for (int j = 0; j < FRAMES_PER_THR; ++j) {
            const int t = t0 + j;
            if (t < TT && s_ni[t] >= THRESH) {
                if (k < LL) s_fidx[k] = t;
                ++k;
            }
        }
    }
    __syncthreads();

    // Build records with exact-f32 reconstruction of weights.
    const int cnt = s_cnt;
    if (tid < LL) {
        int4 r = make_int4(0, -1, 0, 0);
        if (tid < cnt) {
            const int t = s_fidx[tid];
            float iold = 0.0f;
            if (t > 0) {
                const float np = s_ni[t - 1];
                iold = (np >= THRESH) ? __fsub_rn(np, 1.0f) : np;
            }
            const float cur = __fsub_rn(1.0f, iold);
            float carry = 0.0f;
            int prev = -1;
            if (tid > 0) {
                prev = s_fidx[tid - 1];
                float piold = 0.0f;
                if (prev > 0) {
                    const float np = s_ni[prev - 1];
                    piold = (np >= THRESH) ? __fsub_rn(np, 1.0f) : np;
                }
                const float pcur = __fsub_rn(1.0f, piold);
                carry = __fsub_rn(s_alpha[prev], pcur);
            }
            r.x = prev;
            r.y = t;
            r.z = __float_as_int(carry);
            r.w = __float_as_int(cur);
        }
        g_rec[b * LL + tid] = r;
    }
    if (tid == 0) g_cnt[b] = cnt;
}

// ---------------------------------------------------------------------------
// Kernel 2: WARP-granular persistent work-stealing gather.
// Each warp steals one token; each lane owns 4 float4 channel slices
// (lane*4 + j*128 floats). No block-level sync in the steal loop.
// ---------------------------------------------------------------------------
__global__ void __launch_bounds__(128) cif_gather_kernel(
    const float* __restrict__ hidden,   // [B,T,H]
    float* __restrict__ out)            // [B,L,H]
{
    const int lane = threadIdx.x & 31;

    for (;;) {
        int i = 0;
        if (lane == 0) i = atomicAdd(&g_work, 1);
        i = __shfl_sync(0xffffffffu, i, 0);
        if (i >= NTOK) return;

        const int b = i & (BB - 1);     // same-k tokens spread across batches
        const int k = i >> 5;

        float4 acc0 = make_float4(0.f, 0.f, 0.f, 0.f);
        float4 acc1 = make_float4(0.f, 0.f, 0.f, 0.f);
        float4 acc2 = make_float4(0.f, 0.f, 0.f, 0.f);
        float4 acc3 = make_float4(0.f, 0.f, 0.f, 0.f);

        if (k < g_cnt[b]) {
            const int4 r = g_rec[b * LL + k];
            const int   s  = r.x;
            const int   e  = r.y;
            const float wc = __int_as_float(r.z);
            const float we = __int_as_float(r.w);

            const float* hb = hidden + (size_t)b * TT * HH + lane * 4;
            const float* wa = g_walpha + b * TT;

            if (s >= 0) {
                const float4* row = reinterpret_cast<const float4*>(hb + (size_t)s * HH);
                const float4 h0 = row[0];   const float4 h1 = row[32];
                const float4 h2 = row[64];  const float4 h3 = row[96];
                acc0.x += wc * h0.x; acc0.y += wc * h0.y; acc0.z += wc * h0.z; acc0.w += wc * h0.w;
                acc1.x += wc * h1.x; acc1.y += wc * h1.y; acc1.z += wc * h1.z; acc1.w += wc * h1.w;
                acc2.x += wc * h2.x; acc2.y += wc * h2.y; acc2.z += wc * h2.z; acc2.w += wc * h2.w;
                acc3.x += wc * h3.x; acc3.y += wc * h3.y; acc3.z += wc * h3.z; acc3.w += wc * h3.w;
            }
            #pragma unroll 2
            for (int t = s + 1; t < e; ++t) {
                const float w = wa[t];
                const float4* row = reinterpret_cast<const float4*>(hb + (size_t)t * HH);
                const float4 h0 = row[0];   const float4 h1 = row[32];
                const float4 h2 = row[64];  const float4 h3 = row[96];
                acc0.x += w * h0.x; acc0.y += w * h0.y; acc0.z += w * h0.z; acc0.w += w * h0.w;
                acc1.x += w * h1.x; acc1.y += w * h1.y; acc1.z += w * h1.z; acc1.w += w * h1.w;
                acc2.x += w * h2.x; acc2.y += w * h2.y; acc2.z += w * h2.z; acc2.w += w * h2.w;
                acc3.x += w * h3.x; acc3.y += w * h3.y; acc3.z += w * h3.z; acc3.w += w * h3.w;
            }
            {
                const float4* row = reinterpret_cast<const float4*>(hb + (size_t)e * HH);
                const float4 h0 = row[0];   const float4 h1 = row[32];
                const float4 h2 = row[64];  const float4 h3 = row[96];
                acc0.x += we * h0.x; acc0.y += we * h0.y; acc0.z += we * h0.z; acc0.w += we * h0.w;
                acc1.x += we * h1.x; acc1.y += we * h1.y; acc1.z += we * h1.z; acc1.w += we * h1.w;
                acc2.x += we * h2.x; acc2.y += we * h2.y; acc2.z += we * h2.z; acc2.w += we * h2.w;
                acc3.x += we * h3.x; acc3.y += we * h3.y; acc3.z += we * h3.z; acc3.w += we * h3.w;
            }
        }
        float4* ob = reinterpret_cast<float4*>(out + ((size_t)b * LL + k) * HH + lane * 4);
        ob[0]  = acc0;
        ob[32] = acc1;
        ob[64] = acc2;
        ob[96] = acc3;
    }
}

// ---------------------------------------------------------------------------
extern "C" void kernel_launch(void* const* d_in, const int* in_sizes, int n_in,
                              void* d_out, int out_size)
{
    const float* hidden = (const float*)d_in[0];   // [B,T,H] f32
    const float* alphas = (const float*)d_in[1];   // [B,T]   f32
    const int*   tlen   = (const int*)  d_in[2];   // [B]     i32
    float* out = (float*)d_out;                    // [B,L,H] f32

    cif_scan_kernel<<<BB + NPF, NTHR>>>(hidden, alphas, tlen);
    cif_gather_kernel<<<GBLK, 128>>>(hidden, out);
}

// round 14
// speedup vs baseline: 1.0257x; 1.0257x over previous
#include <cuda_runtime.h>
#include <cstdint>

// Problem constants (fixed by the reference).
#define BB 32
#define TT 2000
#define LL 256
#define HH 512
#define NTHR 256
#define FRAMES_PER_THR 8   // 256*8 = 2048 >= 2000
#define T4 (TT / 4)        // 500 float4 groups
#define THRESH 0.95f
#define NTOK (BB * LL)     // 8192 tokens
#define GBLK 1184          // 148 SMs * 8 CTAs (x4 warps = 4736 stealing warps)

// Prefetch role (R10 passing form): 1000 blocks x 256 thr x 4 x 128B = all of hidden.
#define NPF 1000
#define PF_PER_THR 4

// Scratch (allocation-free rule: __device__ globals).
__device__ float g_walpha[BB * TT];   // rescaled alphas
__device__ int4  g_rec[BB * LL];      // {seg_start, seg_end, carry_bits, cur_bits}
__device__ int   g_cnt[BB];           // fires per batch (clamped to LL)
__device__ int   g_work;              // work-stealing counter (reset by scan)

// One CIF recurrence step, forced to the short data chain:
//   add.f32 -> {setp.ge ; sub.f32 in parallel} -> selp.f32 (pred-as-data)
__device__ __forceinline__ void cif_step(float& integ, float a, float& ni_out)
{
    float ni, nim;
    asm("add.f32 %0, %2, %3;\n\t"
        "sub.f32 %1, %0, 0f3F800000;"            // nim = ni - 1.0f
        : "=f"(ni), "=f"(nim) : "f"(integ), "f"(a));
    asm("{\n\t"
        ".reg .pred p;\n\t"
        "setp.ge.f32 p, %1, 0f3F733333;\n\t"     // ni >= 0.95f
        "selp.f32 %0, %2, %1, p;\n\t"
        "}"
        : "=f"(integ) : "f"(ni), "f"(nim));
    ni_out = ni;
}

// ---------------------------------------------------------------------------
// Kernel 1 (R10 passing form): blocks [0,32) = scan role; blocks [32,32+NPF)
// = L2 prefetch of hidden under the scan's serial shadow.
// ---------------------------------------------------------------------------
__global__ void __launch_bounds__(NTHR, 1) cif_scan_kernel(
    const float* __restrict__ hidden,   // [B,T,H] (prefetch only)
    const float* __restrict__ alphas,   // [B,T]
    const int*   __restrict__ tlen)     // [B]
{
    const int tid = threadIdx.x;

    if (blockIdx.x >= BB) {
        // ---- Prefetch role: 128 KB contiguous slice per block ----
        const size_t base = (size_t)(blockIdx.x - BB) * (NTHR * PF_PER_THR * 128)
                          + (size_t)tid * 128;
        const char* p = reinterpret_cast<const char*>(hidden) + base;
        #pragma unroll
        for (int i = 0; i < PF_PER_THR; ++i)
            asm volatile("prefetch.global.L2 [%0];"
                         :: "l"(p + (size_t)i * NTHR * 128));
        return;
    }

    __shared__ __align__(16) float s_alpha[TT];
    __shared__ __align__(16) float s_ni[TT];
    __shared__ double s_wred[8];
    __shared__ float  s_scale;
    __shared__ int    s_tsum[NTHR];
    __shared__ int    s_fidx[LL];
    __shared__ int    s_cnt;

    const int b    = blockIdx.x;
    const int lane = tid & 31;
    const int wid  = tid >> 5;

    if (b == 0 && tid == 0) g_work = 0;   // reset for the following gather

    // ---- Phase 1: load alphas (float4), double sum via warp shuffles ----
    const float4* ain = reinterpret_cast<const float4*>(alphas + b * TT);
    float4* asm4 = reinterpret_cast<float4*>(s_alpha);
    double local = 0.0;
    #pragma unroll
    for (int i = 0; i < 2; ++i) {
        const int idx = tid + i * NTHR;
        if (idx < T4) {
            const float4 v = ain[idx];
            asm4[idx] = v;
            local += (double)v.x + (double)v.y + (double)v.z + (double)v.w;
        }
    }
    #pragma unroll
    for (int off = 16; off > 0; off >>= 1)
        local += __shfl_down_sync(0xffffffffu, local, off);
    if (lane == 0) s_wred[wid] = local;
    __syncthreads();
    if (tid == 0) {
        double s = 0.0;
        #pragma unroll
        for (int w = 0; w < 8; ++w) s += s_wred[w];
        s_scale = __fdiv_rn((float)tlen[b], (float)s);
    }
    __syncthreads();

    // ---- Rescale (smem + spill to global) ----
    const float scale = s_scale;
    float4* wout = reinterpret_cast<float4*>(g_walpha + b * TT);
    #pragma unroll
    for (int i = 0; i < 2; ++i) {
        const int idx = tid + i * NTHR;
        if (idx < T4) {
            float4 v = asm4[idx];
            v.x = __fmul_rn(v.x, scale); v.y = __fmul_rn(v.y, scale);
            v.z = __fmul_rn(v.z, scale); v.w = __fmul_rn(v.w, scale);
            asm4[idx] = v;
            wout[idx] = v;
        }
    }
    __syncthreads();

    // ---- Phase 2: minimal serial recurrence (thread 0), prefetched ----
    if (tid == 0) {
        float integ = 0.0f;
        const float4* a4 = reinterpret_cast<const float4*>(s_alpha);
        float4* n4 = reinterpret_cast<float4*>(s_ni);
        float4 av = a4[0];
        #pragma unroll 2
        for (int t4 = 0; t4 < T4; ++t4) {
            const int nidx = (t4 + 1 < T4) ? t4 + 1 : t4;
            const float4 nx = a4[nidx];       // prefetch off-chain
            float4 nv;
            cif_step(integ, av.x, nv.x);
            cif_step(integ, av.y, nv.y);
            cif_step(integ, av.z, nv.z);
            cif_step(integ, av.w, nv.w);
            n4[t4] = nv;
            av = nx;
        }
    }
    __syncthreads();

    // ---- Phase 3: parallel rebuild of fire records from ni_t ----
    const int t0 = tid * FRAMES_PER_THR;
    int cnt_local = 0;
    #pragma unroll
    for (int j = 0; j < FRAMES_PER_THR; ++j) {
        const int t = t0 + j;
        if (t < TT && s_ni[t] >= THRESH) ++cnt_local;
    }
    s_tsum[tid] = cnt_local;
    __syncthreads();

    {   // exclusive prefix sum over 256 counts
        int v = s_tsum[tid];
        int x = v;
        #pragma unroll
        for (int d = 1; d < 32; d <<= 1) {
            int y = __shfl_up_sync(0xffffffffu, x, d);
            if (lane >= d) x += y;
        }
        __syncthreads();
        if (lane == 31) s_tsum[wid] = x;
        __syncthreads();
        int warp_base = 0, total = 0;
        #pragma unroll
        for (int w = 0; w < 8; ++w) {
            const int wv = s_tsum[w];
            warp_base += (w < wid) ? wv : 0;
            total += wv;
        }
        __syncthreads();
        s_tsum[tid] = warp_base + x - v;
        if (tid == 0) s_cnt = (total < LL) ? total : LL;
    }
    __syncthreads();

    {   // compact fire frame indices
        int k = s_tsum[tid];
        #pragma unroll
        for (int j = 0; j < FRAMES_PER_THR; ++j) {
            const int t = t0 + j;
            if (t < TT && s_ni[t] >= THRESH) {
                if (k < LL) s_fidx[k] = t;
                ++k;
            }
        }
    }
    __syncthreads();

    // Build records with exact-f32 reconstruction of weights.
    const int cnt = s_cnt;
    if (tid < LL) {
        int4 r = make_int4(0, -1, 0, 0);
        if (tid < cnt) {
            const int t = s_fidx[tid];
            float iold = 0.0f;
            if (t > 0) {
                const float np = s_ni[t - 1];
                iold = (np >= THRESH) ? __fsub_rn(np, 1.0f) : np;
            }
            const float cur = __fsub_rn(1.0f, iold);
            float carry = 0.0f;
            int prev = -1;
            if (tid > 0) {
                prev = s_fidx[tid - 1];
                float piold = 0.0f;
                if (prev > 0) {
                    const float np = s_ni[prev - 1];
                    piold = (np >= THRESH) ? __fsub_rn(np, 1.0f) : np;
                }
                const float pcur = __fsub_rn(1.0f, piold);
                carry = __fsub_rn(s_alpha[prev], pcur);
            }
            r.x = prev;
            r.y = t;
            r.z = __float_as_int(carry);
            r.w = __float_as_int(cur);
        }
        g_rec[b * LL + tid] = r;
    }
    if (tid == 0) g_cnt[b] = cnt;
}

// ---------------------------------------------------------------------------
// Kernel 2: WARP-granular persistent work-stealing gather.
// Each warp steals one token; each lane owns 4 float4 channel slices
// (lane*4 + j*128 floats). No block-level sync in the steal loop.
// ---------------------------------------------------------------------------
__global__ void __launch_bounds__(128) cif_gather_kernel(
    const float* __restrict__ hidden,   // [B,T,H]
    float* __restrict__ out)            // [B,L,H]
{
    const int lane = threadIdx.x & 31;

    for (;;) {
        int i = 0;
        if (lane == 0) i = atomicAdd(&g_work, 1);
        i = __shfl_sync(0xffffffffu, i, 0);
        if (i >= NTOK) return;

        const int b = i & (BB - 1);     // same-k tokens spread across batches
        const int k = i >> 5;

        float4 acc0 = make_float4(0.f, 0.f, 0.f, 0.f);
        float4 acc1 = make_float4(0.f, 0.f, 0.f, 0.f);
        float4 acc2 = make_float4(0.f, 0.f, 0.f, 0.f);
        float4 acc3 = make_float4(0.f, 0.f, 0.f, 0.f);

        if (k < g_cnt[b]) {
            const int4 r = g_rec[b * LL + k];
            const int   s  = r.x;
            const int   e  = r.y;
            const float wc = __int_as_float(r.z);
            const float we = __int_as_float(r.w);

            const float* hb = hidden + (size_t)b * TT * HH + lane * 4;
            const float* wa = g_walpha + b * TT;

            if (s >= 0) {
                const float4* row = reinterpret_cast<const float4*>(hb + (size_t)s * HH);
                const float4 h0 = row[0];   const float4 h1 = row[32];
                const float4 h2 = row[64];  const float4 h3 = row[96];
                acc0.x += wc * h0.x; acc0.y += wc * h0.y; acc0.z += wc * h0.z; acc0.w += wc * h0.w;
                acc1.x += wc * h1.x; acc1.y += wc * h1.y; acc1.z += wc * h1.z; acc1.w += wc * h1.w;
                acc2.x += wc * h2.x; acc2.y += wc * h2.y; acc2.z += wc * h2.z; acc2.w += wc * h2.w;
                acc3.x += wc * h3.x; acc3.y += wc * h3.y; acc3.z += wc * h3.z; acc3.w += wc * h3.w;
            }
            #pragma unroll 2
            for (int t = s + 1; t < e; ++t) {
                const float w = wa[t];
                const float4* row = reinterpret_cast<const float4*>(hb + (size_t)t * HH);
                const float4 h0 = row[0];   const float4 h1 = row[32];
                const float4 h2 = row[64];  const float4 h3 = row[96];
                acc0.x += w * h0.x; acc0.y += w * h0.y; acc0.z += w * h0.z; acc0.w += w * h0.w;
                acc1.x += w * h1.x; acc1.y += w * h1.y; acc1.z += w * h1.z; acc1.w += w * h1.w;
                acc2.x += w * h2.x; acc2.y += w * h2.y; acc2.z += w * h2.z; acc2.w += w * h2.w;
                acc3.x += w * h3.x; acc3.y += w * h3.y; acc3.z += w * h3.z; acc3.w += w * h3.w;
            }
            {
                const float4* row = reinterpret_cast<const float4*>(hb + (size_t)e * HH);
                const float4 h0 = row[0];   const float4 h1 = row[32];
                const float4 h2 = row[64];  const float4 h3 = row[96];
                acc0.x += we * h0.x; acc0.y += we * h0.y; acc0.z += we * h0.z; acc0.w += we * h0.w;
                acc1.x += we * h1.x; acc1.y += we * h1.y; acc1.z += we * h1.z; acc1.w += we * h1.w;
                acc2.x += we * h2.x; acc2.y += we * h2.y; acc2.z += we * h2.z; acc2.w += we * h2.w;
                acc3.x += we * h3.x; acc3.y += we * h3.y; acc3.z += we * h3.z; acc3.w += we * h3.w;
            }
        }
        float4* ob = reinterpret_cast<float4*>(out + ((size_t)b * LL + k) * HH + lane * 4);
        ob[0]  = acc0;
        ob[32] = acc1;
        ob[64] = acc2;
        ob[96] = acc3;
    }
}

// ---------------------------------------------------------------------------
extern "C" void kernel_launch(void* const* d_in, const int* in_sizes, int n_in,
                              void* d_out, int out_size)
{
    const float* hidden = (const float*)d_in[0];   // [B,T,H] f32
    const float* alphas = (const float*)d_in[1];   // [B,T]   f32
    const int*   tlen   = (const int*)  d_in[2];   // [B]     i32
    float* out = (float*)d_out;                    // [B,L,H] f32

    cif_scan_kernel<<<BB + NPF, NTHR>>>(hidden, alphas, tlen);
    cif_gather_kernel<<<GBLK, 128>>>(hidden, out);
}

// round 17
// speedup vs baseline: 1.1868x; 1.1571x over previous
#include <cuda_runtime.h>
#include <cstdint>

// Problem constants (fixed by the reference).
#define BB 32
#define TT 2000
#define LL 256
#define HH 512
#define NTHR 256
#define FRAMES_PER_THR 8   // 256*8 = 2048 >= 2000
#define T4 (TT / 4)        // 500 float4 groups
#define THRESH 0.95f
#define NTOK (BB * LL)     // 8192 tokens
#define GBLK 2368          // 148 SMs * 16 CTAs (CTA-granular stealing)

// Prefetch role: 512 blocks = 16 per batch; each block pulls 128 KB of the
// FIRST 2 MB (first 1024 frames) of its batch into L2. Total 64 MB ~= the
// serial scan's DRAM shadow (~14 us at ~4.5 TB/s).
#define NPF 512
#define PF_PER_THR 4

// Scratch (allocation-free rule: __device__ globals).
__device__ float g_walpha[BB * TT];   // rescaled alphas
__device__ int4  g_rec[BB * LL];      // {seg_start, seg_end, carry_bits, cur_bits}
__device__ int   g_cnt[BB];           // fires per batch (clamped to LL)
__device__ int   g_work;              // work-stealing counter (reset by scan)

// One CIF recurrence step, forced to the short data chain:
//   add.f32 -> {setp.ge ; sub.f32 in parallel} -> selp.f32 (pred-as-data)
__device__ __forceinline__ void cif_step(float& integ, float a, float& ni_out)
{
    float ni, nim;
    asm("add.f32 %0, %2, %3;\n\t"
        "sub.f32 %1, %0, 0f3F800000;"            // nim = ni - 1.0f
        : "=f"(ni), "=f"(nim) : "f"(integ), "f"(a));
    asm("{\n\t"
        ".reg .pred p;\n\t"
        "setp.ge.f32 p, %1, 0f3F733333;\n\t"     // ni >= 0.95f
        "selp.f32 %0, %2, %1, p;\n\t"
        "}"
        : "=f"(integ) : "f"(ni), "f"(nim));
    ni_out = ni;
}

// ---------------------------------------------------------------------------
// Kernel 1: blocks [0,32) = scan role. Blocks [32, 32+NPF) = L2 prefetch of
// the first 1024 frames of each batch (matches gather's ascending-k order).
// ---------------------------------------------------------------------------
__global__ void __launch_bounds__(NTHR, 1) cif_scan_kernel(
    const float* __restrict__ hidden,   // [B,T,H] (prefetch only)
    const float* __restrict__ alphas,   // [B,T]
    const int*   __restrict__ tlen)     // [B]
{
    const int tid = threadIdx.x;

    if (blockIdx.x >= BB) {
        // ---- Prefetch role ----
        const int p  = blockIdx.x - BB;       // 0..511
        const int pb = p >> 4;                // batch 0..31
        const int pj = p & 15;                // 128KB slice within first 2MB
        const size_t base = (size_t)pb * ((size_t)TT * HH * 4)
                          + (size_t)pj * (NTHR * PF_PER_THR * 128)
                          + (size_t)tid * 128;
        const char* q = reinterpret_cast<const char*>(hidden) + base;
        #pragma unroll
        for (int i = 0; i < PF_PER_THR; ++i)
            asm volatile("prefetch.global.L2 [%0];"
                         :: "l"(q + (size_t)i * NTHR * 128));
        return;
    }

    __shared__ __align__(16) float s_alpha[TT];
    __shared__ __align__(16) float s_ni[TT];
    __shared__ double s_wred[8];
    __shared__ float  s_scale;
    __shared__ int    s_tsum[NTHR];
    __shared__ int    s_fidx[LL];
    __shared__ int    s_cnt;

    const int b    = blockIdx.x;
    const int lane = tid & 31;
    const int wid  = tid >> 5;

    if (b == 0 && tid == 0) g_work = 0;   // reset for the following gather

    // ---- Phase 1: load alphas (float4), double sum via warp shuffles ----
    const float4* ain = reinterpret_cast<const float4*>(alphas + b * TT);
    float4* asm4 = reinterpret_cast<float4*>(s_alpha);
    double local = 0.0;
    #pragma unroll
    for (int i = 0; i < 2; ++i) {
        const int idx = tid + i * NTHR;
        if (idx < T4) {
            const float4 v = ain[idx];
            asm4[idx] = v;
            local += (double)v.x + (double)v.y + (double)v.z + (double)v.w;
        }
    }
    #pragma unroll
    for (int off = 16; off > 0; off >>= 1)
        local += __shfl_down_sync(0xffffffffu, local, off);
    if (lane == 0) s_wred[wid] = local;
    __syncthreads();
    if (tid == 0) {
        double s = 0.0;
        #pragma unroll
        for (int w = 0; w < 8; ++w) s += s_wred[w];
        s_scale = __fdiv_rn((float)tlen[b], (float)s);
    }
    __syncthreads();

    // ---- Rescale (smem + spill to global) ----
    const float scale = s_scale;
    float4* wout = reinterpret_cast<float4*>(g_walpha + b * TT);
    #pragma unroll
    for (int i = 0; i < 2; ++i) {
        const int idx = tid + i * NTHR;
        if (idx < T4) {
            float4 v = asm4[idx];
            v.x = __fmul_rn(v.x, scale); v.y = __fmul_rn(v.y, scale);
            v.z = __fmul_rn(v.z, scale); v.w = __fmul_rn(v.w, scale);
            asm4[idx] = v;
            wout[idx] = v;
        }
    }
    __syncthreads();

    // ---- Phase 2: minimal serial recurrence (thread 0), prefetched ----
    if (tid == 0) {
        float integ = 0.0f;
        const float4* a4 = reinterpret_cast<const float4*>(s_alpha);
        float4* n4 = reinterpret_cast<float4*>(s_ni);
        float4 av = a4[0];
        #pragma unroll 2
        for (int t4 = 0; t4 < T4; ++t4) {
            const int nidx = (t4 + 1 < T4) ? t4 + 1 : t4;
            const float4 nx = a4[nidx];       // prefetch off-chain
            float4 nv;
            cif_step(integ, av.x, nv.x);
            cif_step(integ, av.y, nv.y);
            cif_step(integ, av.z, nv.z);
            cif_step(integ, av.w, nv.w);
            n4[t4] = nv;
            av = nx;
        }
    }
    __syncthreads();

    // ---- Phase 3: parallel rebuild of fire records from ni_t ----
    const int t0 = tid * FRAMES_PER_THR;
    int cnt_local = 0;
    #pragma unroll
    for (int j = 0; j < FRAMES_PER_THR; ++j) {
        const int t = t0 + j;
        if (t < TT && s_ni[t] >= THRESH) ++cnt_local;
    }
    s_tsum[tid] = cnt_local;
    __syncthreads();

    {   // exclusive prefix sum over 256 counts
        int v = s_tsum[tid];
        int x = v;
        #pragma unroll
        for (int d = 1; d < 32; d <<= 1) {
            int y = __shfl_up_sync(0xffffffffu, x, d);
            if (lane >= d) x += y;
        }
        __syncthreads();
        if (lane == 31) s_tsum[wid] = x;
        __syncthreads();
        int warp_base = 0, total = 0;
        #pragma unroll
        for (int w = 0; w < 8; ++w) {
            const int wv = s_tsum[w];
            warp_base += (w < wid) ? wv : 0;
            total += wv;
        }
        __syncthreads();
        s_tsum[tid] = warp_base + x - v;
        if (tid == 0) s_cnt = (total < LL) ? total : LL;
    }
    __syncthreads();

    {   // compact fire frame indices
        int k = s_tsum[tid];
        #pragma unroll
        for (int j = 0; j < FRAMES_PER_THR; ++j) {
            const int t = t0 + j;
            if (t < TT && s_ni[t] >= THRESH) {
                if (k < LL) s_fidx[k] = t;
                ++k;
            }
        }
    }
    __syncthreads();

    // Build records with exact-f32 reconstruction of weights.
    const int cnt = s_cnt;
    if (tid < LL) {
        int4 r = make_int4(0, -1, 0, 0);
        if (tid < cnt) {
            const int t = s_fidx[tid];
            float iold = 0.0f;
            if (t > 0) {
                const float np = s_ni[t - 1];
                iold = (np >= THRESH) ? __fsub_rn(np, 1.0f) : np;
            }
            const float cur = __fsub_rn(1.0f, iold);
            float carry = 0.0f;
            int prev = -1;
            if (tid > 0) {
                prev = s_fidx[tid - 1];
                float piold = 0.0f;
                if (prev > 0) {
                    const float np = s_ni[prev - 1];
                    piold = (np >= THRESH) ? __fsub_rn(np, 1.0f) : np;
                }
                const float pcur = __fsub_rn(1.0f, piold);
                carry = __fsub_rn(s_alpha[prev], pcur);
            }
            r.x = prev;
            r.y = t;
            r.z = __float_as_int(carry);
            r.w = __float_as_int(cur);
        }
        g_rec[b * LL + tid] = r;
    }
    if (tid == 0) g_cnt[b] = cnt;
}

// ---------------------------------------------------------------------------
// Kernel 2: CTA-granular persistent work-stealing gather (R9 measured-best
// form: regs 32, occ ~90%). Do not touch the inner loop.
// ---------------------------------------------------------------------------
__global__ void __launch_bounds__(128) cif_gather_kernel(
    const float* __restrict__ hidden,   // [B,T,H]
    float* __restrict__ out)            // [B,L,H]
{
    __shared__ int s_i;
    const int tid = threadIdx.x;
    const int c   = tid * 4;            // channel base

    for (;;) {
        if (tid == 0) s_i = atomicAdd(&g_work, 1);
        __syncthreads();
        const int i = s_i;
        __syncthreads();                // all threads read s_i before next write
        if (i >= NTOK) return;

        const int b = i & (BB - 1);     // same-k tokens spread across batches
        const int k = i >> 5;

        float4 acc = make_float4(0.f, 0.f, 0.f, 0.f);

        if (k < g_cnt[b]) {
            const int4 r = g_rec[b * LL + k];
            const int   s  = r.x;
            const int   e  = r.y;
            const float wc = __int_as_float(r.z);
            const float we = __int_as_float(r.w);

            const float* hb = hidden + (size_t)b * TT * HH;
            const float* wa = g_walpha + b * TT;

            if (s >= 0) {
                const float4 h4 = *reinterpret_cast<const float4*>(hb + (size_t)s * HH + c);
                acc.x += wc * h4.x; acc.y += wc * h4.y;
                acc.z += wc * h4.z; acc.w += wc * h4.w;
            }
            #pragma unroll 4
            for (int t = s + 1; t < e; ++t) {
                const float w = wa[t];
                const float4 h4 = *reinterpret_cast<const float4*>(hb + (size_t)t * HH + c);
                acc.x += w * h4.x; acc.y += w * h4.y;
                acc.z += w * h4.z; acc.w += w * h4.w;
            }
            {
                const float4 h4 = *reinterpret_cast<const float4*>(hb + (size_t)e * HH + c);
                acc.x += we * h4.x; acc.y += we * h4.y;
                acc.z += we * h4.z; acc.w += we * h4.w;
            }
        }
        *reinterpret_cast<float4*>(out + ((size_t)b * LL + k) * HH + c) = acc;
    }
}

// ---------------------------------------------------------------------------
extern "C" void kernel_launch(void* const* d_in, const int* in_sizes, int n_in,
                              void* d_out, int out_size)
{
    const float* hidden = (const float*)d_in[0];   // [B,T,H] f32
    const float* alphas = (const float*)d_in[1];   // [B,T]   f32
    const int*   tlen   = (const int*)  d_in[2];   // [B]     i32
    float* out = (float*)d_out;                    // [B,L,H] f32

    cif_scan_kernel<<<BB + NPF, NTHR>>>(hidden, alphas, tlen);
    cif_gather_kernel<<<GBLK, 128>>>(hidden, out);
}